// round 14
// baseline (speedup 1.0000x reference)
#include <cuda_runtime.h>

#define N_NODES 50000
#define N_EDGES 200000
#define F_IN 100
#define HID 1024

#define NB_FOLD  (F_IN + 1)                        // 101 fold blocks
#define NB_DEG   ((N_NODES + 255) / 256)           // 196 per-node blocks
#define NB_EDGE  ((N_EDGES + 255) / 256)           // 782 edge blocks (1/thr)
#define NB_NODE  ((N_NODES * 32 + 255) / 256)      // 6250 dot blocks (warp/node)

// Scratch (no device allocation allowed).
// g_deg starts 0 (zero-init) and is reset to 0 by K3 (coalesced
// read-then-zero) every run -> each graph replay sees a clean accumulator.
__device__ float g_w[F_IN];
__device__ float g_c;
__device__ float g_deg[N_NODES];
__device__ float g_dinv[N_NODES];
__device__ float g_s[N_NODES];
__device__ float g_p[N_NODES];

// Per-block edge-dtype detect (input-only): int64-LE values < 50000 have
// all-zero odd 32-bit words; 128 random int32 endpoints all zero: prob ~ 0.
__device__ __forceinline__ bool detect_is64_inline(const int* __restrict__ ebuf) {
    __shared__ int nz;
    if (threadIdx.x == 0) nz = 0;
    __syncthreads();
    if (threadIdx.x < 128 && ebuf[2 * threadIdx.x + 1] != 0) nz = 1;
    __syncthreads();
    return nz == 0;
}

// ---------------------------------------------------------------------------
// K1: fold w = W1 @ W_head (and c = b1·W_head + b_head). Nothing else.
// ---------------------------------------------------------------------------
__global__ void __launch_bounds__(256)
setup_kernel(const float* __restrict__ W1,
             const float* __restrict__ b1,
             const float* __restrict__ Wh,
             const float* __restrict__ bh) {
    int blk = blockIdx.x;
    int t = threadIdx.x;
    __shared__ float red[256];
    float acc = 0.f;
    if (blk < F_IN) {
        const float* row = W1 + (long long)blk * HID;
        for (int k = t; k < HID; k += 256) acc += row[k] * Wh[k];
    } else {
        for (int k = t; k < HID; k += 256) acc += b1[k] * Wh[k];
    }
    red[t] = acc;
    __syncthreads();
    for (int s = 128; s > 0; s >>= 1) {
        if (t < s) red[t] += red[t + s];
        __syncthreads();
    }
    if (t == 0) {
        if (blk < F_IN) g_w[blk] = red[0];
        else            g_c     = red[0] + bh[0];
    }
}

// ---------------------------------------------------------------------------
// K2 (PDL): edge blocks first (deg atomics onto zero-based counter — NO
// dependency sync needed, K1 never touches g_deg); dot blocks after
// (s[n] = x[n]·w; SCALAR 4-load prologue = MLP 4 per thread, proven).
// ---------------------------------------------------------------------------
__global__ void __launch_bounds__(256)
dot_and_deg_kernel(const float* __restrict__ x,
                   const int* __restrict__ ebuf) {
    int blk = blockIdx.x;
    int t = threadIdx.x;

    if (blk < NB_EDGE) {
        bool is64 = detect_is64_inline(ebuf);
        int e = blk * 256 + t;
        if (e < N_EDGES) {
            long long pos = (long long)N_EDGES + e;
            int dst = is64 ? ((const int2*)ebuf)[pos].x : ebuf[pos];
            if ((unsigned)dst < N_NODES)
                atomicAdd(&g_deg[dst], 1.0f);   // overlaps K1's fold fully
        }
        return;
    }

    int node = ((blk - NB_EDGE) * 256 + t) >> 5;
    int lane = t & 31;

    // prologue: 4 independent scalar loads per thread (input only)
    float x0 = 0.f, x1 = 0.f, x2 = 0.f, x3 = 0.f;
    if (node < N_NODES) {
        const float* xr = x + (long long)node * F_IN;
        x0 = xr[lane];
        x1 = xr[lane + 32];
        x2 = xr[lane + 64];
        if (lane < 4) x3 = xr[lane + 96];
    }

    cudaGridDependencySynchronize();           // g_w ready

    __shared__ float sw[F_IN];
    for (int i = t; i < F_IN; i += 256) sw[i] = g_w[i];
    __syncthreads();
    if (node >= N_NODES) return;

    float acc = x0 * sw[lane] + x1 * sw[lane + 32] + x2 * sw[lane + 64];
    if (lane < 4) acc += x3 * sw[lane + 96];

    #pragma unroll
    for (int o = 16; o > 0; o >>= 1)
        acc += __shfl_down_sync(0xffffffffu, acc, o);

    if (lane == 0) g_s[node] = acc;
}

// ---------------------------------------------------------------------------
// K3 (PDL): per-node finalize (coalesced): dinv, p, out-init; resets g_deg
// to 0 for the next graph replay (read-then-zero, same thread).
// ---------------------------------------------------------------------------
__global__ void __launch_bounds__(256)
node_finalize(float* __restrict__ out) {
    cudaGridDependencySynchronize();           // deg atomics + s complete
    int n = blockIdx.x * blockDim.x + threadIdx.x;
    if (n < N_NODES) {
        float deg = g_deg[n] + 1.0f;           // +1 self loop (zero-based counter)
        g_deg[n] = 0.0f;                       // restore for next replay
        float d = rsqrtf(deg);
        float s = g_s[n];
        g_dinv[n] = d;
        g_p[n]    = s * d;
        out[n]    = g_c + s * d * d;           // self-loop msg + folded bias
    }
}

// ---------------------------------------------------------------------------
// K4 (PDL): edge scatter, 1 edge/thread, 782 blocks (~42 warps/SM -> 2x the
// latency-hiding warps vs the 391-block 2-edge version).
// Edge decode (input only) runs before the dependency sync.
// ---------------------------------------------------------------------------
__global__ void __launch_bounds__(256)
edge_scatter(const int* __restrict__ ebuf,
             float* __restrict__ out) {
    bool is64 = detect_is64_inline(ebuf);
    int e = blockIdx.x * 256 + threadIdx.x;

    int s0 = -1, d0 = -1;
    if (e < N_EDGES) {
        if (is64) {
            s0 = ((const int2*)ebuf)[e].x;
            d0 = ((const int2*)ebuf)[(long long)N_EDGES + e].x;
        } else {
            s0 = ebuf[e];
            d0 = ebuf[(long long)N_EDGES + e];
        }
    }
    bool v0 = (unsigned)s0 < N_NODES && (unsigned)d0 < N_NODES;

    cudaGridDependencySynchronize();           // p, dinv, out-init complete

    float p0 = v0 ? g_p[s0] : 0.f;
    float q0 = v0 ? g_dinv[d0] : 0.f;

    if (v0) atomicAdd(&out[d0], p0 * q0);
}

// ---------------------------------------------------------------------------
// Host: PDL launches (programmatic stream serialization)
// ---------------------------------------------------------------------------
template <typename... Args>
static inline void launch_pdl(void (*kern)(Args...), dim3 grid, Args... args) {
    cudaLaunchConfig_t cfg = {};
    cudaLaunchAttribute attr[1];
    attr[0].id = cudaLaunchAttributeProgrammaticStreamSerialization;
    attr[0].val.programmaticStreamSerializationAllowed = 1;
    cfg.gridDim = grid;
    cfg.blockDim = dim3(256, 1, 1);
    cfg.dynamicSmemBytes = 0;
    cfg.stream = 0;
    cfg.attrs = attr;
    cfg.numAttrs = 1;
    cudaLaunchKernelEx(&cfg, kern, args...);
}

extern "C" void kernel_launch(void* const* d_in, const int* in_sizes, int n_in,
                              void* d_out, int out_size) {
    const float* state = (const float*)d_in[0];  // [N, 100, 1] f32
    const int*   ebuf  = (const int*)  d_in[1];  // [2, 200000] int32/int64 layout
    const float* W1    = (const float*)d_in[2];  // [100, 1024]
    const float* b1    = (const float*)d_in[3];  // [1024]
    const float* Wh    = (const float*)d_in[4];  // [1024, 1]
    const float* bh    = (const float*)d_in[5];  // [1]
    float* out = (float*)d_out;                  // [N, 1]

    setup_kernel<<<NB_FOLD, 256>>>(W1, b1, Wh, bh);
    launch_pdl(dot_and_deg_kernel, dim3(NB_EDGE + NB_NODE, 1, 1), state, ebuf);
    launch_pdl(node_finalize, dim3(NB_DEG, 1, 1), (float*)out);
    launch_pdl(edge_scatter, dim3(NB_EDGE, 1, 1), (const int*)ebuf, (float*)out);
}

// round 15
// speedup vs baseline: 1.1366x; 1.1366x over previous
#include <cuda_runtime.h>

#define N_NODES 50000
#define N_EDGES 200000
#define F_IN 100
#define HID 1024

#define NB_FOLD  (F_IN + 1)                        // 101 fold blocks
#define NB_DEG   ((N_NODES + 255) / 256)           // 196 per-node blocks
#define NB_E4    ((N_EDGES / 4 + 255) / 256)       // 196 deg blocks (4 edges/thr)
#define NB_NODE  ((N_NODES * 32 + 255) / 256)      // 6250 dot blocks (warp/node)
#define NB_E2    ((N_EDGES / 2 + 255) / 256)       // 391 scatter blocks (2/thr)

// Scratch (no device allocation allowed).
// g_deg starts 0 (zero-init) and is reset to 0 by K3 (coalesced
// read-then-zero) every run -> each graph replay sees a clean accumulator.
__device__ float g_w[F_IN];
__device__ float g_c;
__device__ float g_deg[N_NODES];
__device__ float g_dinv[N_NODES];
__device__ float g_s[N_NODES];
__device__ float g_p[N_NODES];

// Per-block edge-dtype detect (input-only): int64-LE values < 50000 have
// all-zero odd 32-bit words; 128 random int32 endpoints all zero: prob ~ 0.
__device__ __forceinline__ bool detect_is64_inline(const int* __restrict__ ebuf) {
    __shared__ int nz;
    if (threadIdx.x == 0) nz = 0;
    __syncthreads();
    if (threadIdx.x < 128 && ebuf[2 * threadIdx.x + 1] != 0) nz = 1;
    __syncthreads();
    return nz == 0;
}

// ---------------------------------------------------------------------------
// K1: fold w = W1 @ W_head (and c = b1·W_head + b_head). Nothing else.
// ---------------------------------------------------------------------------
__global__ void __launch_bounds__(256)
setup_kernel(const float* __restrict__ W1,
             const float* __restrict__ b1,
             const float* __restrict__ Wh,
             const float* __restrict__ bh) {
    int blk = blockIdx.x;
    int t = threadIdx.x;
    __shared__ float red[256];
    float acc = 0.f;
    if (blk < F_IN) {
        const float* row = W1 + (long long)blk * HID;
        for (int k = t; k < HID; k += 256) acc += row[k] * Wh[k];
    } else {
        for (int k = t; k < HID; k += 256) acc += b1[k] * Wh[k];
    }
    red[t] = acc;
    __syncthreads();
    for (int s = 128; s > 0; s >>= 1) {
        if (t < s) red[t] += red[t + s];
        __syncthreads();
    }
    if (t == 0) {
        if (blk < F_IN) g_w[blk] = red[0];
        else            g_c     = red[0] + bh[0];
    }
}

// ---------------------------------------------------------------------------
// K2 (PDL): deg blocks first — now only 196 blocks at 4 edges/thread with
// int4-vectorized index loads (frees ~600 wave-1 slots for dot blocks, so
// the 20 MB x-stream starts earlier). No dependency sync needed for them
// (K1 never touches g_deg). Dot blocks after (scalar 4-load prologue).
// ---------------------------------------------------------------------------
__global__ void __launch_bounds__(256)
dot_and_deg_kernel(const float* __restrict__ x,
                   const int* __restrict__ ebuf) {
    int blk = blockIdx.x;
    int t = threadIdx.x;

    if (blk < NB_E4) {
        bool is64 = detect_is64_inline(ebuf);
        int e = (blk * 256 + t) * 4;
        if (e < N_EDGES) {   // N_EDGES % 4 == 0: no partial batches
            int d0, d1, d2, d3;
            if (is64) {
                long long base = ((long long)N_EDGES + e) >> 1;  // int4 units
                int4 v0 = ((const int4*)ebuf)[base];
                int4 v1 = ((const int4*)ebuf)[base + 1];
                d0 = v0.x; d1 = v0.z; d2 = v1.x; d3 = v1.z;
            } else {
                int4 v = ((const int4*)ebuf)[((long long)N_EDGES + e) >> 2];
                d0 = v.x; d1 = v.y; d2 = v.z; d3 = v.w;
            }
            if ((unsigned)d0 < N_NODES) atomicAdd(&g_deg[d0], 1.0f);
            if ((unsigned)d1 < N_NODES) atomicAdd(&g_deg[d1], 1.0f);
            if ((unsigned)d2 < N_NODES) atomicAdd(&g_deg[d2], 1.0f);
            if ((unsigned)d3 < N_NODES) atomicAdd(&g_deg[d3], 1.0f);
        }
        return;
    }

    int node = ((blk - NB_E4) * 256 + t) >> 5;
    int lane = t & 31;

    // prologue: 4 independent scalar loads per thread (input only, MLP 4)
    float x0 = 0.f, x1 = 0.f, x2 = 0.f, x3 = 0.f;
    if (node < N_NODES) {
        const float* xr = x + (long long)node * F_IN;
        x0 = xr[lane];
        x1 = xr[lane + 32];
        x2 = xr[lane + 64];
        if (lane < 4) x3 = xr[lane + 96];
    }

    cudaGridDependencySynchronize();           // g_w ready

    __shared__ float sw[F_IN];
    for (int i = t; i < F_IN; i += 256) sw[i] = g_w[i];
    __syncthreads();
    if (node >= N_NODES) return;

    float acc = x0 * sw[lane] + x1 * sw[lane + 32] + x2 * sw[lane + 64];
    if (lane < 4) acc += x3 * sw[lane + 96];

    #pragma unroll
    for (int o = 16; o > 0; o >>= 1)
        acc += __shfl_down_sync(0xffffffffu, acc, o);

    if (lane == 0) g_s[node] = acc;
}

// ---------------------------------------------------------------------------
// K3 (PDL): per-node finalize (coalesced): dinv, p, out-init; resets g_deg
// to 0 for the next graph replay (read-then-zero, same thread).
// ---------------------------------------------------------------------------
__global__ void __launch_bounds__(256)
node_finalize(float* __restrict__ out) {
    cudaGridDependencySynchronize();           // deg atomics + s complete
    int n = blockIdx.x * blockDim.x + threadIdx.x;
    if (n < N_NODES) {
        float deg = g_deg[n] + 1.0f;           // +1 self loop (zero-based counter)
        g_deg[n] = 0.0f;                       // restore for next replay
        float d = rsqrtf(deg);
        float s = g_s[n];
        g_dinv[n] = d;
        g_p[n]    = s * d;
        out[n]    = g_c + s * d * d;           // self-loop msg + folded bias
    }
}

// ---------------------------------------------------------------------------
// K4 (PDL): edge scatter, 2 edges/thread (PROVEN optimum): out[dst] +=
// p[src] * dinv[dst]. Edge decode (input only) runs before the sync.
// ---------------------------------------------------------------------------
__global__ void __launch_bounds__(256)
edge_scatter(const int* __restrict__ ebuf,
             float* __restrict__ out) {
    bool is64 = detect_is64_inline(ebuf);
    int e = (blockIdx.x * 256 + threadIdx.x) * 2;

    int s0 = -1, s1 = -1, d0 = -1, d1 = -1;
    if (e < N_EDGES) {   // N_EDGES even: no partial pairs
        if (is64) {
            int4 vs = ((const int4*)ebuf)[e >> 1];
            int4 vd = ((const int4*)ebuf)[((long long)N_EDGES + e) >> 1];
            s0 = vs.x; s1 = vs.z; d0 = vd.x; d1 = vd.z;
        } else {
            int2 vs = ((const int2*)ebuf)[e >> 1];
            int2 vd = ((const int2*)ebuf)[((long long)N_EDGES + e) >> 1];
            s0 = vs.x; s1 = vs.y; d0 = vd.x; d1 = vd.y;
        }
    }
    bool v0 = (unsigned)s0 < N_NODES && (unsigned)d0 < N_NODES;
    bool v1 = (unsigned)s1 < N_NODES && (unsigned)d1 < N_NODES;

    cudaGridDependencySynchronize();           // p, dinv, out-init complete

    float p0 = v0 ? g_p[s0] : 0.f;
    float p1 = v1 ? g_p[s1] : 0.f;
    float q0 = v0 ? g_dinv[d0] : 0.f;
    float q1 = v1 ? g_dinv[d1] : 0.f;

    if (v0) atomicAdd(&out[d0], p0 * q0);
    if (v1) atomicAdd(&out[d1], p1 * q1);
}

// ---------------------------------------------------------------------------
// Host: PDL launches (programmatic stream serialization)
// ---------------------------------------------------------------------------
template <typename... Args>
static inline void launch_pdl(void (*kern)(Args...), dim3 grid, Args... args) {
    cudaLaunchConfig_t cfg = {};
    cudaLaunchAttribute attr[1];
    attr[0].id = cudaLaunchAttributeProgrammaticStreamSerialization;
    attr[0].val.programmaticStreamSerializationAllowed = 1;
    cfg.gridDim = grid;
    cfg.blockDim = dim3(256, 1, 1);
    cfg.dynamicSmemBytes = 0;
    cfg.stream = 0;
    cfg.attrs = attr;
    cfg.numAttrs = 1;
    cudaLaunchKernelEx(&cfg, kern, args...);
}

extern "C" void kernel_launch(void* const* d_in, const int* in_sizes, int n_in,
                              void* d_out, int out_size) {
    const float* state = (const float*)d_in[0];  // [N, 100, 1] f32
    const int*   ebuf  = (const int*)  d_in[1];  // [2, 200000] int32/int64 layout
    const float* W1    = (const float*)d_in[2];  // [100, 1024]
    const float* b1    = (const float*)d_in[3];  // [1024]
    const float* Wh    = (const float*)d_in[4];  // [1024, 1]
    const float* bh    = (const float*)d_in[5];  // [1]
    float* out = (float*)d_out;                  // [N, 1]

    setup_kernel<<<NB_FOLD, 256>>>(W1, b1, Wh, bh);
    launch_pdl(dot_and_deg_kernel, dim3(NB_E4 + NB_NODE, 1, 1), state, ebuf);
    launch_pdl(node_finalize, dim3(NB_DEG, 1, 1), (float*)out);
    launch_pdl(edge_scatter, dim3(NB_E2, 1, 1), (const int*)ebuf, (float*)out);
}